// round 17
// baseline (speedup 1.0000x reference)
#include <cuda_runtime.h>
#include <cuda_fp16.h>
#include <math.h>
#include <stdint.h>

#define B_ 16
#define S_ 2048
#define D_ 256
#define NT 256
#define LOG2E 1.4426950408889634f

// ================= compacted fp16 scratch =================
__device__ __half g_Khi[(size_t)B_*D_*S_];   // [b][d][jc]  compacted cols
__device__ __half g_Vhi[(size_t)B_*S_*D_];   // [b][jc][dv] compacted rows
__device__ int    g_nb[B_];
__device__ int    g_idx[(size_t)B_*S_];

__device__ __forceinline__ uint32_t smem_u32(const void* p) {
    uint32_t a;
    asm("{ .reg .u64 t; cvta.to.shared.u64 t, %1; cvt.u32.u64 %0, t; }" : "=r"(a) : "l"(p));
    return a;
}

// fast exp2 on fma/alu pipes (no MUFU)
__device__ __forceinline__ float exp2p(float y) {
    y = fmaxf(y, -125.f);
    float z = __fadd_rn(y, 12582912.f);
    int   n = __float_as_int(z) - 0x4B400000;
    float f = __fsub_rn(y, __fadd_rn(z, -12582912.f));
    float p = 1.33335581e-3f;
    p = fmaf(p, f, 9.61812910e-3f);
    p = fmaf(p, f, 5.55041087e-2f);
    p = fmaf(p, f, 2.40226512e-1f);
    p = fmaf(p, f, 6.93147182e-1f);
    p = fmaf(p, f, 1.0f);
    return __int_as_float(__float_as_int(p) + (n << 23));
}

#define LDSM4(r, a) \
    asm volatile("ldmatrix.sync.aligned.m8n8.x4.shared.b16 {%0,%1,%2,%3}, [%4];" \
        : "=r"((r)[0]), "=r"((r)[1]), "=r"((r)[2]), "=r"((r)[3]) : "r"(a))

#define LDSM4T(r, a) \
    asm volatile("ldmatrix.sync.aligned.m8n8.x4.trans.shared.b16 {%0,%1,%2,%3}, [%4];" \
        : "=r"((r)[0]), "=r"((r)[1]), "=r"((r)[2]), "=r"((r)[3]) : "r"(a))

#define MMA(d, a, b0, b1) \
    asm volatile("mma.sync.aligned.m16n8k16.row.col.f32.f16.f16.f32 " \
        "{%0,%1,%2,%3},{%4,%5,%6,%7},{%8,%9},{%0,%1,%2,%3};" \
        : "+f"((d)[0]), "+f"((d)[1]), "+f"((d)[2]), "+f"((d)[3]) \
        : "r"((a)[0]), "r"((a)[1]), "r"((a)[2]), "r"((a)[3]), "r"(b0), "r"(b1))

#define PACKH2(d, lo, hi) \
    asm("cvt.rn.f16x2.f32 %0, %1, %2;" : "=r"(d) : "f"(hi), "f"(lo))

#define CPASYNC16(dst, src) \
    asm volatile("cp.async.cg.shared.global [%0], [%1], 16;" :: "r"(dst), "l"(src))
#define CPCOMMIT()   asm volatile("cp.async.commit_group;" ::: "memory")
#define CPWAIT_ALL() asm volatile("cp.async.wait_group 0;" ::: "memory")

// ================= prep kernels =================
__global__ void build_idx(const int* __restrict__ mask) {
    __shared__ int s0[256], s1[256];
    const int b = blockIdx.x, t = threadIdx.x;
    const int* mb = mask + (size_t)b * S_;
    int my[8], c = 0;
    #pragma unroll
    for (int i = 0; i < 8; i++) { my[i] = mb[t * 8 + i]; c += (my[i] != 0); }
    s0[t] = c;
    __syncthreads();
    int* in = s0; int* out = s1;
    for (int d = 1; d < 256; d <<= 1) {
        out[t] = in[t] + ((t >= d) ? in[t - d] : 0);
        __syncthreads();
        int* tmp = in; in = out; out = tmp;
    }
    int pos = in[t] - c;
    #pragma unroll
    for (int i = 0; i < 8; i++)
        if (my[i]) g_idx[(size_t)b * S_ + (pos++)] = t * 8 + i;
    if (t == 255) g_nb[b] = in[255];
}

// gather K (hi only): out [b][d][jc], zero pad to 64-multiple
__global__ void gather_k(const float* __restrict__ k) {
    size_t i = (size_t)blockIdx.x * blockDim.x + threadIdx.x;  // over B*D*(S/4)
    int jc4 = (int)(i % (S_ / 4)) * 4;
    size_t bd = i / (S_ / 4);
    int b = (int)(bd / D_);
    int nb = g_nb[b];
    int npad = (nb + 63) & ~63;
    if (jc4 >= npad) return;
    const int* idx = g_idx + (size_t)b * S_;
    const float* krow = k + bd * S_;
    __half h[4];
    #pragma unroll
    for (int t = 0; t < 4; t++) {
        int jc = jc4 + t;
        float x = (jc < nb) ? krow[idx[jc]] : 0.f;
        h[t] = __float2half_rn(x);
    }
    *(uint2*)(g_Khi + bd * S_ + jc4) = *(uint2*)h;
}

// gather V rows: out [b][jc][dv], zero pad; 256-thr blocks, 4 rows each
__global__ void gather_v(const float* __restrict__ v) {
    const int b = blockIdx.y, t = threadIdx.x;
    const int jc = blockIdx.x * 4 + (t >> 6);
    const int col = t & 63;
    int nb = g_nb[b];
    int npad = (nb + 63) & ~63;
    if (jc >= npad) return;
    __half h[4] = {__half(0.f), __half(0.f), __half(0.f), __half(0.f)};
    if (jc < nb) {
        int j = g_idx[(size_t)b * S_ + jc];
        float4 f = *(const float4*)(v + ((size_t)b * S_ + j) * D_ + col * 4);
        h[0] = __float2half_rn(f.x); h[1] = __float2half_rn(f.y);
        h[2] = __float2half_rn(f.z); h[3] = __float2half_rn(f.w);
    }
    *(uint2*)(g_Vhi + ((size_t)b * S_ + jc) * D_ + col * 4) = *(uint2*)h;
}

// ================= main kernel =================
// Q: [128 q][256 d] hi/lo, rows 512B                     (128 KB)
// K: [256 d][64 j]  hi, rows 128B, single buf            ( 32 KB)
// V: [64 j][256 dv] hi, rows 512B, single buf            ( 32 KB)
#define QSP    65536
#define OFF_K  131072
#define OFF_V  163840
#define SMEM_SZ 196608

__global__ void __launch_bounds__(NT, 1)
attn_hmma(const float* __restrict__ qf, float* __restrict__ out)
{
    extern __shared__ char smem[];
    const uint32_t sb = smem_u32(smem);
    const int tid  = threadIdx.x;
    const int lane = tid & 31;
    const int warp = tid >> 5;
    const int b    = blockIdx.y;
    const int q0   = blockIdx.x * 128;

    const __half* khb = g_Khi + (size_t)b * D_ * S_;
    const __half* vhb = g_Vhi + (size_t)b * S_ * D_;
    const float*  qsrc = qf + ((size_t)b * S_ + q0) * D_;
    const int nbv = g_nb[b];
    const int ntiles = (nbv + 63) >> 6;

    // ---- prologue: Q fp32 -> hi/lo; staging spans K+V regions (64 KB) ----
    #pragma unroll
    for (int p = 0; p < 2; p++) {
        #pragma unroll
        for (int it = 0; it < 16; it++) {
            int idx = tid + it * NT;
            int r = idx >> 6, c = idx & 63;
            CPASYNC16(sb + OFF_K + r * 1024 + c * 16,
                      qsrc + (size_t)(64 * p + r) * D_ + c * 4);
        }
        CPCOMMIT();
        CPWAIT_ALL();
        __syncthreads();
        #pragma unroll
        for (int it = 0; it < 8; it++) {
            int idx = tid + it * NT;
            int rl = idx >> 5, u = idx & 31;
            int r = 64 * p + rl;
            float4 f0 = *(const float4*)(smem + OFF_K + rl * 1024 + u * 32);
            float4 f1 = *(const float4*)(smem + OFF_K + rl * 1024 + u * 32 + 16);
            __half2 h01 = __floats2half2_rn(f0.x, f0.y);
            __half2 h23 = __floats2half2_rn(f0.z, f0.w);
            __half2 h45 = __floats2half2_rn(f1.x, f1.y);
            __half2 h67 = __floats2half2_rn(f1.z, f1.w);
            float2 g01 = __half22float2(h01), g23 = __half22float2(h23);
            float2 g45 = __half22float2(h45), g67 = __half22float2(h67);
            __half2 l01 = __floats2half2_rn(f0.x - g01.x, f0.y - g01.y);
            __half2 l23 = __floats2half2_rn(f0.z - g23.x, f0.w - g23.y);
            __half2 l45 = __floats2half2_rn(f1.x - g45.x, f1.y - g45.y);
            __half2 l67 = __floats2half2_rn(f1.z - g67.x, f1.w - g67.y);
            uint32_t off = r * 512 + ((u ^ (r & 7)) << 4);
            *(uint4*)(smem + off)       = make_uint4(*(uint32_t*)&h01, *(uint32_t*)&h23,
                                                     *(uint32_t*)&h45, *(uint32_t*)&h67);
            *(uint4*)(smem + off + QSP) = make_uint4(*(uint32_t*)&l01, *(uint32_t*)&l23,
                                                     *(uint32_t*)&l45, *(uint32_t*)&l67);
        }
        __syncthreads();
    }

    // ---- issue K(0): 256 d-rows x 8 units ----
    #pragma unroll
    for (int it = 0; it < 8; it++) {
        int idx = tid + it * NT;
        int r = idx >> 3, u = idx & 7;
        uint32_t dst = sb + OFF_K + r * 128 + ((u ^ (r & 7)) << 4);
        CPASYNC16(dst, khb + (size_t)r * S_ + u * 8);
    }
    CPCOMMIT();

    // ---- lane geometry ----
    const int mrow = lane & 7;
    const int rowA = warp * 16 + mrow + (((lane >> 3) & 1) << 3);
    const int hiA  = lane >> 4;
    const int krb  = ((lane >> 3) & 1) * 8 + (lane & 7);
    const int ul   = lane >> 4;

    uint32_t aQ[4];
    #pragma unroll
    for (int m = 0; m < 4; m++)
        aQ[m] = sb + rowA * 512 + ((((2 * m + hiA)) ^ mrow) << 4);

    uint32_t kbs[4], vrel[4];
    #pragma unroll
    for (int nn = 0; nn < 4; nn++)
        kbs[nn] = (uint32_t)(krb * 128 + (((2 * nn + ul) ^ (krb & 7)) << 4));
    #pragma unroll
    for (int i = 0; i < 4; i++)
        vrel[i] = (uint32_t)(krb * 512 + (((i * 2 + ul) ^ (krb & 7)) << 4));

    float O[32][4];
    #pragma unroll
    for (int i = 0; i < 32; i++) { O[i][0] = O[i][1] = O[i][2] = O[i][3] = 0.f; }
    float mr0 = -INFINITY, mr1 = -INFINITY, lr0 = 0.f, lr1 = 0.f;

    const int c2 = (lane & 3) * 2;
    const int g  = lane >> 2;

    for (int jt = 0; jt < ntiles; jt++) {
        const int kt = jt * 64;

        CPWAIT_ALL();          // K(jt) ready
        __syncthreads();       // all warps done GEMM2(jt-1) -> V buffer free

        // ---- issue V(jt): 64 j-rows x 32 units (overlaps GEMM1) ----
        #pragma unroll
        for (int it = 0; it < 8; it++) {
            int idx = tid + it * NT;
            int r = idx >> 5, u = idx & 31;
            uint32_t dst = sb + OFF_V + r * 512 + ((u >> 3) << 7)
                         + (((u & 7) ^ (r & 7)) << 4);
            CPASYNC16(dst, vhb + (size_t)(kt + r) * D_ + u * 8);
        }
        CPCOMMIT();

        // ---- GEMM1 (3-buf, distance-2 pipelined): S = Qhi*Khi + Qlo*Khi ----
        float s[8][4];
        #pragma unroll
        for (int i = 0; i < 8; i++) s[i][0] = s[i][1] = s[i][2] = s[i][3] = 0.f;

        {
            uint32_t A0[2][4], A1[2][4], BB[3][4];
            LDSM4(A0[0], aQ[0]);
            LDSM4(A1[0], aQ[0] + QSP);
            LDSM4T(BB[0], sb + OFF_K + kbs[0]);
            LDSM4T(BB[1], sb + OFF_K + kbs[1]);
            #pragma unroll
            for (int st = 0; st < 64; st++) {
                const int kk = st >> 2, nn = st & 3;
                const int cA = kk & 1, cB = st % 3;
                // prefetch B frag 2 steps ahead -> 3rd buffer (no WAR window)
                if (st < 62) {
                    const int stn = st + 2;
                    LDSM4T(BB[(st + 2) % 3],
                           sb + OFF_K + (stn >> 2) * 2048 + kbs[stn & 3]);
                }
                // prefetch A frags one kk ahead
                if (nn == 1 && kk < 15) {
                    const uint32_t an = aQ[(kk + 1) & 3] + ((kk + 1) >> 2) * 128;
                    LDSM4(A0[cA ^ 1], an);
                    LDSM4(A1[cA ^ 1], an + QSP);
                }
                // accumulator-distance-2 order; per-acc sequence (hi then lo) preserved
                MMA(s[2*nn],   A0[cA], BB[cB][0], BB[cB][1]);
                MMA(s[2*nn+1], A0[cA], BB[cB][2], BB[cB][3]);
                MMA(s[2*nn],   A1[cA], BB[cB][0], BB[cB][1]);
                MMA(s[2*nn+1], A1[cA], BB[cB][2], BB[cB][3]);
            }
        }

        CPWAIT_ALL();          // V(jt) ready
        __syncthreads();       // all warps done GEMM1 -> K buffer free

        // ---- issue K(jt+1) NOW (overlaps softmax + GEMM2; clamped on last) ----
        {
            const int ktn = ((jt + 1 < ntiles) ? jt + 1 : jt) * 64;
            #pragma unroll
            for (int it = 0; it < 8; it++) {
                int idx = tid + it * NT;
                int r = idx >> 3, u = idx & 7;
                uint32_t dst = sb + OFF_K + r * 128 + ((u ^ (r & 7)) << 4);
                CPASYNC16(dst, khb + (size_t)r * S_ + ktn + u * 8);
            }
            CPCOMMIT();
        }

        // ---- preload first two V frags (latency hidden under softmax) ----
        // step st addresses: OFF_V + (st>>4)*8192 + vrel[st&3] + (((st&15)>>2)<<7)
        // st=0 -> vrel[0]; st=1 -> vrel[1] (nn>>2 == 0, no +128!)
        uint32_t VB[3][4];
        LDSM4T(VB[0], sb + OFF_V + vrel[0]);
        LDSM4T(VB[1], sb + OFF_V + vrel[1]);

        // ---- tail guard + online softmax ----
        uint32_t Ph[8][2];
        {
            if (jt == ntiles - 1) {
                #pragma unroll
                for (int nf = 0; nf < 8; nf++) {
                    int col = kt + nf * 8 + c2;
                    if (col     >= nbv) { s[nf][0] = -1.0e9f; s[nf][2] = -1.0e9f; }
                    if (col + 1 >= nbv) { s[nf][1] = -1.0e9f; s[nf][3] = -1.0e9f; }
                }
            }
            float m0 = -INFINITY, m1 = -INFINITY;
            #pragma unroll
            for (int nf = 0; nf < 8; nf++) {
                m0 = fmaxf(m0, fmaxf(s[nf][0], s[nf][1]));
                m1 = fmaxf(m1, fmaxf(s[nf][2], s[nf][3]));
            }
            m0 = fmaxf(m0, __shfl_xor_sync(0xffffffffu, m0, 1));
            m0 = fmaxf(m0, __shfl_xor_sync(0xffffffffu, m0, 2));
            m1 = fmaxf(m1, __shfl_xor_sync(0xffffffffu, m1, 1));
            m1 = fmaxf(m1, __shfl_xor_sync(0xffffffffu, m1, 2));

            float mn0 = fmaxf(mr0, m0), mn1 = fmaxf(mr1, m1);
            float sc0 = exp2p((mr0 - mn0) * LOG2E);
            float sc1 = exp2p((mr1 - mn1) * LOG2E);
            mr0 = mn0; mr1 = mn1;
            float nb0 = -mn0 * LOG2E, nb1 = -mn1 * LOG2E;
            float rs0 = 0.f, rs1 = 0.f;

            #pragma unroll
            for (int nf = 0; nf < 8; nf++) {
                float p0 = exp2p(fmaf(s[nf][0], LOG2E, nb0));
                float p1 = exp2p(fmaf(s[nf][1], LOG2E, nb0));
                float p2 = exp2p(fmaf(s[nf][2], LOG2E, nb1));
                float p3 = exp2p(fmaf(s[nf][3], LOG2E, nb1));
                rs0 += p0 + p1;
                rs1 += p2 + p3;
                PACKH2(Ph[nf][0], p0, p1);
                PACKH2(Ph[nf][1], p2, p3);
            }
            lr0 = lr0 * sc0 + rs0;
            lr1 = lr1 * sc1 + rs1;

            if (__any_sync(0xffffffffu, (sc0 != 1.0f) || (sc1 != 1.0f))) {
                #pragma unroll
                for (int i = 0; i < 32; i++) {
                    O[i][0] *= sc0; O[i][1] *= sc0;
                    O[i][2] *= sc1; O[i][3] *= sc1;
                }
            }
        }

        // ---- GEMM2 (3-buf, distance-2 pipelined): O += P * Vhi ----
        {
            #pragma unroll
            for (int st = 0; st < 64; st++) {
                const int kk = st >> 4, nn = st & 15;
                const int c = st % 3;
                if (st < 62) {
                    const int stn = st + 2;
                    const int kk2 = stn >> 4, nn2 = stn & 15;
                    LDSM4T(VB[(st + 2) % 3],
                           sb + OFF_V + kk2 * 8192 + vrel[nn2 & 3] + ((nn2 >> 2) << 7));
                }
                uint32_t ap[4] = { Ph[2*kk][0], Ph[2*kk][1],
                                   Ph[2*kk+1][0], Ph[2*kk+1][1] };
                MMA(O[2*nn],   ap, VB[c][0], VB[c][1]);
                MMA(O[2*nn+1], ap, VB[c][2], VB[c][3]);
            }
        }
    }
    CPWAIT_ALL();

    // ---- epilogue ----
    lr0 += __shfl_xor_sync(0xffffffffu, lr0, 1);
    lr0 += __shfl_xor_sync(0xffffffffu, lr0, 2);
    lr1 += __shfl_xor_sync(0xffffffffu, lr1, 1);
    lr1 += __shfl_xor_sync(0xffffffffu, lr1, 2);
    float inv0 = 1.f / (lr0 * 16.0f);
    float inv1 = 1.f / (lr1 * 16.0f);

    float* ob = out + (size_t)b * D_ * S_;
    const int qg = q0 + warp * 16 + g;
    #pragma unroll
    for (int nn = 0; nn < 32; nn++) {
        int dv = nn * 8 + c2;
        ob[(size_t)dv * S_ + qg]           = O[nn][0] * inv0;
        ob[(size_t)(dv + 1) * S_ + qg]     = O[nn][1] * inv0;
        ob[(size_t)dv * S_ + qg + 8]       = O[nn][2] * inv1;
        ob[(size_t)(dv + 1) * S_ + qg + 8] = O[nn][3] * inv1;
    }
}

// ================= launcher =================
extern "C" void kernel_launch(void* const* d_in, const int* in_sizes, int n_in,
                              void* d_out, int out_size)
{
    (void)in_sizes; (void)n_in; (void)out_size;
    const float* q    = (const float*)d_in[0];
    const float* k    = (const float*)d_in[1];
    const float* v    = (const float*)d_in[2];
    const int*   mask = (const int*)d_in[3];
    float* out = (float*)d_out;

    build_idx<<<B_, 256>>>(mask);
    {
        size_t total = (size_t)B_ * D_ * (S_ / 4);
        gather_k<<<(unsigned)((total + 255) / 256), 256>>>(k);
    }
    gather_v<<<dim3(S_ / 4, B_), 256>>>(v);

    cudaFuncSetAttribute(attn_hmma, cudaFuncAttributeMaxDynamicSharedMemorySize, SMEM_SZ);
    attn_hmma<<<dim3(S_ / 128, B_), NT, SMEM_SZ>>>(q, out);
}